// round 3
// baseline (speedup 1.0000x reference)
#include <cuda_runtime.h>

#define NN   100000
#define EE   1600000
#define IND  128
#define HID  128
#define EMBD 64
#define KC   100

// ---------------- scratch (static device globals; no allocation) -------------
__device__ float g_dis[NN];            // deg, then deg^-1/2
__device__ float g_H[NN * HID];        // x @ W1
__device__ float g_AGG1[NN * HID];     // scatter result -> h1 (post bias/selfloop)
__device__ float g_H2[NN * EMBD];      // relu(bn(h1)) @ W2
__device__ float g_AGG2[NN * EMBD];    // scatter result layer 2
__device__ float g_sum[HID];
__device__ float g_sumsq[HID];
__device__ float g_scale[HID];
__device__ float g_shift[HID];

// ---------------- init: zero accumulators, deg=1 (self loop) -----------------
__global__ void k_init() {
    int i = blockIdx.x * blockDim.x + threadIdx.x;
    if (i < NN * HID)  g_AGG1[i] = 0.f;
    if (i < NN * EMBD) g_AGG2[i] = 0.f;
    if (i < NN)        g_dis[i]  = 1.0f;
    if (i < HID)       { g_sum[i] = 0.f; g_sumsq[i] = 0.f; }
}

__global__ void k_degree(const int* __restrict__ ei) {
    int e = blockIdx.x * blockDim.x + threadIdx.x;
    if (e < EE) {
        int dst = ei[EE + e];
        if ((unsigned)dst < NN) atomicAdd(&g_dis[dst], 1.0f);
    }
}

__global__ void k_rsqrt() {
    int i = blockIdx.x * blockDim.x + threadIdx.x;
    if (i < NN) g_dis[i] = rsqrtf(g_dis[i]);   // deg >= 1 always (self loops)
}

// ---------------- GEMM1: H = x @ W1   (N x 128) @ (128 x 128) ----------------
// BM=64, BN=128, BK=32, 256 threads, thread tile 4x8
__global__ void k_gemm1(const float* __restrict__ x, const float* __restrict__ W) {
    __shared__ float Xs[64 * 33];
    __shared__ float Ws[32 * 128];
    int tid  = threadIdx.x;
    int row0 = blockIdx.x * 64;
    int tx   = tid & 15;         // 16 col groups of 8
    int ty   = tid >> 4;         // 16 row groups of 4
    int col0 = tx * 8;
    int r0   = ty * 4;

    float acc[4][8];
#pragma unroll
    for (int i = 0; i < 4; i++)
#pragma unroll
        for (int j = 0; j < 8; j++) acc[i][j] = 0.f;

    for (int kk = 0; kk < 128; kk += 32) {
#pragma unroll
        for (int i = 0; i < 8; i++) {          // 2048 = 64x32 X elements
            int idx = i * 256 + tid;
            int r = idx >> 5, k = idx & 31;
            int gr = row0 + r;
            Xs[r * 33 + k] = (gr < NN) ? x[gr * 128 + kk + k] : 0.f;
        }
#pragma unroll
        for (int i = 0; i < 16; i++) {         // 4096 = 32x128 W elements
            int idx = i * 256 + tid;
            int k = idx >> 7, j = idx & 127;
            Ws[k * 128 + j] = W[(kk + k) * 128 + j];
        }
        __syncthreads();
#pragma unroll
        for (int k = 0; k < 32; k++) {
            float4 w0 = *(const float4*)&Ws[k * 128 + col0];
            float4 w1 = *(const float4*)&Ws[k * 128 + col0 + 4];
            float wv[8] = {w0.x, w0.y, w0.z, w0.w, w1.x, w1.y, w1.z, w1.w};
#pragma unroll
            for (int i = 0; i < 4; i++) {
                float xv = Xs[(r0 + i) * 33 + k];
#pragma unroll
                for (int j = 0; j < 8; j++) acc[i][j] = fmaf(xv, wv[j], acc[i][j]);
            }
        }
        __syncthreads();
    }
#pragma unroll
    for (int i = 0; i < 4; i++) {
        int gr = row0 + r0 + i;
        if (gr < NN) {
            float4 o0 = {acc[i][0], acc[i][1], acc[i][2], acc[i][3]};
            float4 o1 = {acc[i][4], acc[i][5], acc[i][6], acc[i][7]};
            *(float4*)&g_H[gr * 128 + col0]     = o0;
            *(float4*)&g_H[gr * 128 + col0 + 4] = o1;
        }
    }
}

// ---------------- scatter 1: warp per edge, 128 features ---------------------
__global__ void k_scatter1(const int* __restrict__ ei) {
    int gw   = (blockIdx.x * blockDim.x + threadIdx.x) >> 5;
    int lane = threadIdx.x & 31;
    if (gw >= EE) return;
    int src = __ldg(&ei[gw]);
    int dst = __ldg(&ei[EE + gw]);
    if ((unsigned)src >= NN || (unsigned)dst >= NN) return;
    float norm = __ldg(&g_dis[src]) * __ldg(&g_dis[dst]);
    float4 v = *(const float4*)&g_H[src * HID + lane * 4];
    float* a = &g_AGG1[dst * HID + lane * 4];
    atomicAdd(a + 0, v.x * norm);
    atomicAdd(a + 1, v.y * norm);
    atomicAdd(a + 2, v.z * norm);
    atomicAdd(a + 3, v.w * norm);
}

// ---------------- self-loop + bias + BN partial sums -------------------------
// 128 threads/block, thread = column, block strides rows
__global__ void k_h1_bn(const float* __restrict__ b1) {
    int c = threadIdx.x;
    float bc = b1[c];
    float s = 0.f, s2 = 0.f;
    for (int r = blockIdx.x; r < NN; r += gridDim.x) {
        float dn = __ldg(&g_dis[r]);
        float sl = dn * dn;
        float v = g_AGG1[r * HID + c] + sl * g_H[r * HID + c] + bc;
        g_AGG1[r * HID + c] = v;
        s += v; s2 += v * v;
    }
    atomicAdd(&g_sum[c], s);
    atomicAdd(&g_sumsq[c], s2);
}

__global__ void k_bn_final(const float* __restrict__ gamma, const float* __restrict__ beta) {
    int c = threadIdx.x;
    float mu   = g_sum[c]   * (1.0f / NN);
    float var  = g_sumsq[c] * (1.0f / NN) - mu * mu;
    float istd = rsqrtf(var + 1e-5f);
    float sc   = istd * gamma[c];
    g_scale[c] = sc;
    g_shift[c] = beta[c] - mu * sc;
}

// ---------------- GEMM2 fused BN+ReLU: H2 = relu(bn(h1)) @ W2 ---------------
// BM=64, BN=64, BK=32, 256 threads, thread tile 2x8
__global__ void k_gemm2(const float* __restrict__ W2) {
    __shared__ float Xs[64 * 33];
    __shared__ float Ws[32 * 64];
    int tid  = threadIdx.x;
    int row0 = blockIdx.x * 64;
    int tx   = tid & 7;          // 8 col groups of 8
    int ty   = tid >> 3;         // 32 row groups of 2
    int col0 = tx * 8;
    int r0   = ty * 2;

    float acc[2][8];
#pragma unroll
    for (int i = 0; i < 2; i++)
#pragma unroll
        for (int j = 0; j < 8; j++) acc[i][j] = 0.f;

    for (int kk = 0; kk < 128; kk += 32) {
#pragma unroll
        for (int i = 0; i < 8; i++) {          // 2048 = 64x32 activations
            int idx = i * 256 + tid;
            int r = idx >> 5, k = idx & 31;
            int gr = row0 + r;
            float v = 0.f;
            if (gr < NN) {
                int cc = kk + k;
                v = g_AGG1[gr * 128 + cc];
                v = fmaf(v, __ldg(&g_scale[cc]), __ldg(&g_shift[cc]));
                v = fmaxf(v, 0.f);
            }
            Xs[r * 33 + k] = v;
        }
#pragma unroll
        for (int i = 0; i < 8; i++) {          // 2048 = 32x64 W elements
            int idx = i * 256 + tid;
            int k = idx >> 6, j = idx & 63;
            Ws[k * 64 + j] = W2[(kk + k) * 64 + j];
        }
        __syncthreads();
#pragma unroll
        for (int k = 0; k < 32; k++) {
            float4 w0 = *(const float4*)&Ws[k * 64 + col0];
            float4 w1 = *(const float4*)&Ws[k * 64 + col0 + 4];
            float wv[8] = {w0.x, w0.y, w0.z, w0.w, w1.x, w1.y, w1.z, w1.w};
#pragma unroll
            for (int i = 0; i < 2; i++) {
                float xv = Xs[(r0 + i) * 33 + k];
#pragma unroll
                for (int j = 0; j < 8; j++) acc[i][j] = fmaf(xv, wv[j], acc[i][j]);
            }
        }
        __syncthreads();
    }
#pragma unroll
    for (int i = 0; i < 2; i++) {
        int gr = row0 + r0 + i;
        if (gr < NN) {
            float4 o0 = {acc[i][0], acc[i][1], acc[i][2], acc[i][3]};
            float4 o1 = {acc[i][4], acc[i][5], acc[i][6], acc[i][7]};
            *(float4*)&g_H2[gr * 64 + col0]     = o0;
            *(float4*)&g_H2[gr * 64 + col0 + 4] = o1;
        }
    }
}

// ---------------- scatter 2: 16 lanes per edge, 64 features ------------------
__global__ void k_scatter2(const int* __restrict__ ei) {
    int gid = blockIdx.x * blockDim.x + threadIdx.x;
    int e = gid >> 4;
    int l = gid & 15;
    if (e >= EE) return;
    int src = __ldg(&ei[e]);
    int dst = __ldg(&ei[EE + e]);
    if ((unsigned)src >= NN || (unsigned)dst >= NN) return;
    float norm = __ldg(&g_dis[src]) * __ldg(&g_dis[dst]);
    float4 v = *(const float4*)&g_H2[src * EMBD + l * 4];
    float* a = &g_AGG2[dst * EMBD + l * 4];
    atomicAdd(a + 0, v.x * norm);
    atomicAdd(a + 1, v.y * norm);
    atomicAdd(a + 2, v.z * norm);
    atomicAdd(a + 3, v.w * norm);
}

// ---------------- final: emb = AGG2 + selfloop + b2; logits; softmax ---------
__global__ void k_final(const float* __restrict__ b2, const float* __restrict__ centers,
                        const float* __restrict__ temp, float* __restrict__ out) {
    __shared__ float Cs[KC * EMBD];   // 25.6 KB
    int tid = threadIdx.x;
    for (int i = tid; i < KC * EMBD; i += blockDim.x) Cs[i] = centers[i];
    __syncthreads();
    int n = blockIdx.x * blockDim.x + tid;
    if (n >= NN) return;

    float dn = g_dis[n];
    float sl = dn * dn;
    float e[EMBD];
    const float4* a4 = (const float4*)&g_AGG2[n * EMBD];
    const float4* h4 = (const float4*)&g_H2[n * EMBD];
    float4* o4 = (float4*)&out[n * EMBD];
#pragma unroll
    for (int i = 0; i < 16; i++) {
        float4 a = a4[i];
        float4 h = h4[i];
        float4 bb = *(const float4*)&b2[i * 4];
        float4 r;
        r.x = a.x + sl * h.x + bb.x;
        r.y = a.y + sl * h.y + bb.y;
        r.z = a.z + sl * h.z + bb.z;
        r.w = a.w + sl * h.w + bb.w;
        e[4 * i + 0] = r.x; e[4 * i + 1] = r.y; e[4 * i + 2] = r.z; e[4 * i + 3] = r.w;
        o4[i] = r;
    }

    float inv_t = 1.0f / temp[0];
    // pass 1: online max + sum(exp)
    float mx = -1e30f, s = 0.f;
    for (int k = 0; k < KC; k++) {
        float d0 = 0.f, d1 = 0.f, d2 = 0.f, d3 = 0.f;
#pragma unroll
        for (int j = 0; j < 16; j++) {
            float4 c = *(const float4*)&Cs[k * EMBD + j * 4];
            d0 = fmaf(e[4 * j + 0], c.x, d0);
            d1 = fmaf(e[4 * j + 1], c.y, d1);
            d2 = fmaf(e[4 * j + 2], c.z, d2);
            d3 = fmaf(e[4 * j + 3], c.w, d3);
        }
        float d = ((d0 + d1) + (d2 + d3)) * inv_t;
        if (d > mx) { s = s * __expf(mx - d) + 1.f; mx = d; }
        else        { s += __expf(d - mx); }
    }
    float inv_s = 1.0f / s;
    float* so = out + (size_t)NN * EMBD + (size_t)n * KC;
    // pass 2: recompute + write softmax
    for (int k = 0; k < KC; k++) {
        float d0 = 0.f, d1 = 0.f, d2 = 0.f, d3 = 0.f;
#pragma unroll
        for (int j = 0; j < 16; j++) {
            float4 c = *(const float4*)&Cs[k * EMBD + j * 4];
            d0 = fmaf(e[4 * j + 0], c.x, d0);
            d1 = fmaf(e[4 * j + 1], c.y, d1);
            d2 = fmaf(e[4 * j + 2], c.z, d2);
            d3 = fmaf(e[4 * j + 3], c.w, d3);
        }
        float d = ((d0 + d1) + (d2 + d3)) * inv_t;
        so[k] = __expf(d - mx) * inv_s;
    }
}

// -----------------------------------------------------------------------------
extern "C" void kernel_launch(void* const* d_in, const int* in_sizes, int n_in,
                              void* d_out, int out_size) {
    const float* x       = (const float*)d_in[0];
    const int*   ei      = (const int*)d_in[1];
    const float* W1      = (const float*)d_in[2];
    const float* b1      = (const float*)d_in[3];
    const float* gamma   = (const float*)d_in[4];
    const float* beta    = (const float*)d_in[5];
    const float* W2      = (const float*)d_in[6];
    const float* b2      = (const float*)d_in[7];
    const float* centers = (const float*)d_in[8];
    const float* temp    = (const float*)d_in[9];
    float* out = (float*)d_out;

    k_init<<<(NN * HID + 255) / 256, 256>>>();
    k_degree<<<(EE + 255) / 256, 256>>>(ei);
    k_rsqrt<<<(NN + 255) / 256, 256>>>();
    k_gemm1<<<(NN + 63) / 64, 256>>>(x, W1);
    k_scatter1<<<(EE * 32 + 255) / 256, 256>>>(ei);
    k_h1_bn<<<2048, 128>>>(b1);
    k_bn_final<<<1, 128>>>(gamma, beta);
    k_gemm2<<<(NN + 63) / 64, 256>>>(W2);
    k_scatter2<<<(EE * 16 + 255) / 256, 256>>>(ei);
    k_final<<<(NN + 255) / 256, 256>>>(b2, centers, temp, out);
}

// round 4
// speedup vs baseline: 1.2414x; 1.2414x over previous
#include <cuda_runtime.h>

#define NN   100000
#define EE   1600000
#define HID  128
#define EMBD 64
#define KC   100
#define NB   98          // ceil(100000/1024) scan blocks

// ---------------- scratch -----------------------------------------------------
__device__ float g_dis[NN];            // deg^-1/2
__device__ float g_H[NN * HID];        // x @ W1
__device__ float g_H1[NN * HID];       // gathered h1 (post selfloop+bias)
__device__ float g_H2[NN * EMBD];      // relu(bn(h1)) @ W2
__device__ float g_EMB[NN * EMBD];     // final embeddings
__device__ float g_sum[HID];
__device__ float g_sumsq[HID];
__device__ float g_scale[HID];
__device__ float g_shift[HID];
// CSR
__device__ int   g_cnt[NN];
__device__ int   g_fill[NN];
__device__ int   g_rowstart[NN + 1];
__device__ int   g_blocksum[NB];
__device__ int   g_blockoff[NB];
__device__ int   g_esrc[EE];
__device__ float g_enorm[EE];

// ---------------- init --------------------------------------------------------
__global__ void k_init() {
    int i = blockIdx.x * blockDim.x + threadIdx.x;
    if (i < NN)  { g_cnt[i] = 0; g_fill[i] = 0; }
    if (i < HID) { g_sum[i] = 0.f; g_sumsq[i] = 0.f; }
}

__global__ void k_count(const int* __restrict__ ei) {
    int e = blockIdx.x * blockDim.x + threadIdx.x;
    if (e < EE) {
        int dst = ei[EE + e];
        if ((unsigned)dst < NN) atomicAdd(&g_cnt[dst], 1);
    }
}

__global__ void k_dis() {
    int i = blockIdx.x * blockDim.x + threadIdx.x;
    if (i < NN) g_dis[i] = rsqrtf((float)(g_cnt[i] + 1));   // +1 self loop
}

// ---------------- scan (3 kernels) -------------------------------------------
__global__ void k_scan1() {              // NB blocks x 1024 threads
    __shared__ int s[1024];
    int t = threadIdx.x;
    int i = blockIdx.x * 1024 + t;
    int v = (i < NN) ? g_cnt[i] : 0;
    s[t] = v;
    __syncthreads();
#pragma unroll
    for (int off = 1; off < 1024; off <<= 1) {
        int add = (t >= off) ? s[t - off] : 0;
        __syncthreads();
        s[t] += add;
        __syncthreads();
    }
    if (i < NN) g_rowstart[i] = s[t] - v;      // exclusive
    if (t == 1023) g_blocksum[blockIdx.x] = s[1023];
}

__global__ void k_scan2() {              // 1 block, 128 threads
    __shared__ int s[128];
    int t = threadIdx.x;
    int v = (t < NB) ? g_blocksum[t] : 0;
    s[t] = v;
    __syncthreads();
#pragma unroll
    for (int off = 1; off < 128; off <<= 1) {
        int add = (t >= off) ? s[t - off] : 0;
        __syncthreads();
        s[t] += add;
        __syncthreads();
    }
    if (t < NB) g_blockoff[t] = s[t] - v;      // exclusive
}

__global__ void k_scan3() {
    int i = blockIdx.x * blockDim.x + threadIdx.x;
    if (i < NN) g_rowstart[i] += g_blockoff[i >> 10];
    if (i == 0) g_rowstart[NN] = EE;
}

__global__ void k_fill(const int* __restrict__ ei) {
    int e = blockIdx.x * blockDim.x + threadIdx.x;
    if (e >= EE) return;
    int src = ei[e];
    int dst = ei[EE + e];
    if ((unsigned)src >= NN || (unsigned)dst >= NN) return;
    int pos = g_rowstart[dst] + atomicAdd(&g_fill[dst], 1);
    g_esrc[pos]  = src;
    g_enorm[pos] = g_dis[src] * g_dis[dst];
}

// ---------------- GEMM1: H = x @ W1 ------------------------------------------
__global__ void k_gemm1(const float* __restrict__ x, const float* __restrict__ W) {
    __shared__ float Xs[64 * 33];
    __shared__ float Ws[32 * 128];
    int tid  = threadIdx.x;
    int row0 = blockIdx.x * 64;
    int tx   = tid & 15;
    int ty   = tid >> 4;
    int col0 = tx * 8;
    int r0   = ty * 4;

    float acc[4][8];
#pragma unroll
    for (int i = 0; i < 4; i++)
#pragma unroll
        for (int j = 0; j < 8; j++) acc[i][j] = 0.f;

    for (int kk = 0; kk < 128; kk += 32) {
#pragma unroll
        for (int i = 0; i < 8; i++) {
            int idx = i * 256 + tid;
            int r = idx >> 5, k = idx & 31;
            int gr = row0 + r;
            Xs[r * 33 + k] = (gr < NN) ? x[gr * 128 + kk + k] : 0.f;
        }
#pragma unroll
        for (int i = 0; i < 16; i++) {
            int idx = i * 256 + tid;
            int k = idx >> 7, j = idx & 127;
            Ws[k * 128 + j] = W[(kk + k) * 128 + j];
        }
        __syncthreads();
#pragma unroll
        for (int k = 0; k < 32; k++) {
            float4 w0 = *(const float4*)&Ws[k * 128 + col0];
            float4 w1 = *(const float4*)&Ws[k * 128 + col0 + 4];
            float wv[8] = {w0.x, w0.y, w0.z, w0.w, w1.x, w1.y, w1.z, w1.w};
#pragma unroll
            for (int i = 0; i < 4; i++) {
                float xv = Xs[(r0 + i) * 33 + k];
#pragma unroll
                for (int j = 0; j < 8; j++) acc[i][j] = fmaf(xv, wv[j], acc[i][j]);
            }
        }
        __syncthreads();
    }
#pragma unroll
    for (int i = 0; i < 4; i++) {
        int gr = row0 + r0 + i;
        if (gr < NN) {
            float4 o0 = {acc[i][0], acc[i][1], acc[i][2], acc[i][3]};
            float4 o1 = {acc[i][4], acc[i][5], acc[i][6], acc[i][7]};
            *(float4*)&g_H[gr * 128 + col0]     = o0;
            *(float4*)&g_H[gr * 128 + col0 + 4] = o1;
        }
    }
}

// ---------------- gather 1: warp per node, 128 feats, fused selfloop+bias ----
__global__ void k_gather1(const float* __restrict__ b1) {
    int w    = (blockIdx.x * blockDim.x + threadIdx.x) >> 5;
    int lane = threadIdx.x & 31;
    if (w >= NN) return;
    int beg = g_rowstart[w], end = g_rowstart[w + 1];
    float4 acc = {0.f, 0.f, 0.f, 0.f};
    int p = beg;
    // 2-way software pipeline for MLP
    for (; p + 2 <= end; p += 2) {
        int   s0 = __ldg(&g_esrc[p]),      s1 = __ldg(&g_esrc[p + 1]);
        float n0 = __ldg(&g_enorm[p]),     n1 = __ldg(&g_enorm[p + 1]);
        float4 v0 = *(const float4*)&g_H[s0 * HID + lane * 4];
        float4 v1 = *(const float4*)&g_H[s1 * HID + lane * 4];
        acc.x = fmaf(v0.x, n0, acc.x); acc.y = fmaf(v0.y, n0, acc.y);
        acc.z = fmaf(v0.z, n0, acc.z); acc.w = fmaf(v0.w, n0, acc.w);
        acc.x = fmaf(v1.x, n1, acc.x); acc.y = fmaf(v1.y, n1, acc.y);
        acc.z = fmaf(v1.z, n1, acc.z); acc.w = fmaf(v1.w, n1, acc.w);
    }
    if (p < end) {
        int   s0 = __ldg(&g_esrc[p]);
        float n0 = __ldg(&g_enorm[p]);
        float4 v0 = *(const float4*)&g_H[s0 * HID + lane * 4];
        acc.x = fmaf(v0.x, n0, acc.x); acc.y = fmaf(v0.y, n0, acc.y);
        acc.z = fmaf(v0.z, n0, acc.z); acc.w = fmaf(v0.w, n0, acc.w);
    }
    float dn = g_dis[w];
    float sl = dn * dn;
    float4 h  = *(const float4*)&g_H[w * HID + lane * 4];
    float4 bb = *(const float4*)&b1[lane * 4];
    acc.x += sl * h.x + bb.x;
    acc.y += sl * h.y + bb.y;
    acc.z += sl * h.z + bb.z;
    acc.w += sl * h.w + bb.w;
    *(float4*)&g_H1[w * HID + lane * 4] = acc;
}

// ---------------- BN stats (read-only) ---------------------------------------
__global__ void k_bnstats() {
    int c = threadIdx.x;
    float s = 0.f, s2 = 0.f;
    for (int r = blockIdx.x; r < NN; r += gridDim.x) {
        float v = g_H1[r * HID + c];
        s += v; s2 += v * v;
    }
    atomicAdd(&g_sum[c], s);
    atomicAdd(&g_sumsq[c], s2);
}

__global__ void k_bn_final(const float* __restrict__ gamma, const float* __restrict__ beta) {
    int c = threadIdx.x;
    float mu   = g_sum[c]   * (1.0f / NN);
    float var  = g_sumsq[c] * (1.0f / NN) - mu * mu;
    float istd = rsqrtf(var + 1e-5f);
    float sc   = istd * gamma[c];
    g_scale[c] = sc;
    g_shift[c] = beta[c] - mu * sc;
}

// ---------------- GEMM2 fused BN+ReLU ----------------------------------------
__global__ void k_gemm2(const float* __restrict__ W2) {
    __shared__ float Xs[64 * 33];
    __shared__ float Ws[32 * 64];
    int tid  = threadIdx.x;
    int row0 = blockIdx.x * 64;
    int tx   = tid & 7;
    int ty   = tid >> 3;
    int col0 = tx * 8;
    int r0   = ty * 2;

    float acc[2][8];
#pragma unroll
    for (int i = 0; i < 2; i++)
#pragma unroll
        for (int j = 0; j < 8; j++) acc[i][j] = 0.f;

    for (int kk = 0; kk < 128; kk += 32) {
#pragma unroll
        for (int i = 0; i < 8; i++) {
            int idx = i * 256 + tid;
            int r = idx >> 5, k = idx & 31;
            int gr = row0 + r;
            float v = 0.f;
            if (gr < NN) {
                int cc = kk + k;
                v = g_H1[gr * 128 + cc];
                v = fmaf(v, __ldg(&g_scale[cc]), __ldg(&g_shift[cc]));
                v = fmaxf(v, 0.f);
            }
            Xs[r * 33 + k] = v;
        }
#pragma unroll
        for (int i = 0; i < 8; i++) {
            int idx = i * 256 + tid;
            int k = idx >> 6, j = idx & 63;
            Ws[k * 64 + j] = W2[(kk + k) * 64 + j];
        }
        __syncthreads();
#pragma unroll
        for (int k = 0; k < 32; k++) {
            float4 w0 = *(const float4*)&Ws[k * 64 + col0];
            float4 w1 = *(const float4*)&Ws[k * 64 + col0 + 4];
            float wv[8] = {w0.x, w0.y, w0.z, w0.w, w1.x, w1.y, w1.z, w1.w};
#pragma unroll
            for (int i = 0; i < 2; i++) {
                float xv = Xs[(r0 + i) * 33 + k];
#pragma unroll
                for (int j = 0; j < 8; j++) acc[i][j] = fmaf(xv, wv[j], acc[i][j]);
            }
        }
        __syncthreads();
    }
#pragma unroll
    for (int i = 0; i < 2; i++) {
        int gr = row0 + r0 + i;
        if (gr < NN) {
            float4 o0 = {acc[i][0], acc[i][1], acc[i][2], acc[i][3]};
            float4 o1 = {acc[i][4], acc[i][5], acc[i][6], acc[i][7]};
            *(float4*)&g_H2[gr * 64 + col0]     = o0;
            *(float4*)&g_H2[gr * 64 + col0 + 4] = o1;
        }
    }
}

// ---------------- gather 2: warp per node, 64 feats (float2/lane) ------------
__global__ void k_gather2(const float* __restrict__ b2) {
    int w    = (blockIdx.x * blockDim.x + threadIdx.x) >> 5;
    int lane = threadIdx.x & 31;
    if (w >= NN) return;
    int beg = g_rowstart[w], end = g_rowstart[w + 1];
    float2 acc = {0.f, 0.f};
    int p = beg;
    for (; p + 2 <= end; p += 2) {
        int   s0 = __ldg(&g_esrc[p]),  s1 = __ldg(&g_esrc[p + 1]);
        float n0 = __ldg(&g_enorm[p]), n1 = __ldg(&g_enorm[p + 1]);
        float2 v0 = *(const float2*)&g_H2[s0 * EMBD + lane * 2];
        float2 v1 = *(const float2*)&g_H2[s1 * EMBD + lane * 2];
        acc.x = fmaf(v0.x, n0, acc.x); acc.y = fmaf(v0.y, n0, acc.y);
        acc.x = fmaf(v1.x, n1, acc.x); acc.y = fmaf(v1.y, n1, acc.y);
    }
    if (p < end) {
        int   s0 = __ldg(&g_esrc[p]);
        float n0 = __ldg(&g_enorm[p]);
        float2 v0 = *(const float2*)&g_H2[s0 * EMBD + lane * 2];
        acc.x = fmaf(v0.x, n0, acc.x); acc.y = fmaf(v0.y, n0, acc.y);
    }
    float dn = g_dis[w];
    float sl = dn * dn;
    float2 h  = *(const float2*)&g_H2[w * EMBD + lane * 2];
    float2 bb = *(const float2*)&b2[lane * 2];
    acc.x += sl * h.x + bb.x;
    acc.y += sl * h.y + bb.y;
    *(float2*)&g_EMB[w * EMBD + lane * 2] = acc;
}

// ---------------- final: copy emb + softmax(logits) --------------------------
__global__ void k_final(const float* __restrict__ centers,
                        const float* __restrict__ temp, float* __restrict__ out) {
    __shared__ float Cs[KC * EMBD];
    int tid = threadIdx.x;
    for (int i = tid; i < KC * EMBD; i += blockDim.x) Cs[i] = centers[i];
    __syncthreads();
    int n = blockIdx.x * blockDim.x + tid;
    if (n >= NN) return;

    float e[EMBD];
    const float4* e4 = (const float4*)&g_EMB[n * EMBD];
    float4* o4 = (float4*)&out[n * EMBD];
#pragma unroll
    for (int i = 0; i < 16; i++) {
        float4 r = e4[i];
        e[4 * i + 0] = r.x; e[4 * i + 1] = r.y; e[4 * i + 2] = r.z; e[4 * i + 3] = r.w;
        o4[i] = r;
    }

    float inv_t = 1.0f / temp[0];
    float mx = -1e30f, s = 0.f;
    for (int k = 0; k < KC; k++) {
        float d0 = 0.f, d1 = 0.f, d2 = 0.f, d3 = 0.f;
#pragma unroll
        for (int j = 0; j < 16; j++) {
            float4 c = *(const float4*)&Cs[k * EMBD + j * 4];
            d0 = fmaf(e[4 * j + 0], c.x, d0);
            d1 = fmaf(e[4 * j + 1], c.y, d1);
            d2 = fmaf(e[4 * j + 2], c.z, d2);
            d3 = fmaf(e[4 * j + 3], c.w, d3);
        }
        float d = ((d0 + d1) + (d2 + d3)) * inv_t;
        if (d > mx) { s = s * __expf(mx - d) + 1.f; mx = d; }
        else        { s += __expf(d - mx); }
    }
    float inv_s = 1.0f / s;
    float* so = out + (size_t)NN * EMBD + (size_t)n * KC;
    for (int k = 0; k < KC; k++) {
        float d0 = 0.f, d1 = 0.f, d2 = 0.f, d3 = 0.f;
#pragma unroll
        for (int j = 0; j < 16; j++) {
            float4 c = *(const float4*)&Cs[k * EMBD + j * 4];
            d0 = fmaf(e[4 * j + 0], c.x, d0);
            d1 = fmaf(e[4 * j + 1], c.y, d1);
            d2 = fmaf(e[4 * j + 2], c.z, d2);
            d3 = fmaf(e[4 * j + 3], c.w, d3);
        }
        float d = ((d0 + d1) + (d2 + d3)) * inv_t;
        so[k] = __expf(d - mx) * inv_s;
    }
}

// -----------------------------------------------------------------------------
extern "C" void kernel_launch(void* const* d_in, const int* in_sizes, int n_in,
                              void* d_out, int out_size) {
    const float* x       = (const float*)d_in[0];
    const int*   ei      = (const int*)d_in[1];
    const float* W1      = (const float*)d_in[2];
    const float* b1      = (const float*)d_in[3];
    const float* gamma   = (const float*)d_in[4];
    const float* beta    = (const float*)d_in[5];
    const float* W2      = (const float*)d_in[6];
    const float* b2      = (const float*)d_in[7];
    const float* centers = (const float*)d_in[8];
    const float* temp    = (const float*)d_in[9];
    float* out = (float*)d_out;

    k_init<<<(NN + 255) / 256, 256>>>();
    k_count<<<(EE + 255) / 256, 256>>>(ei);
    k_dis<<<(NN + 255) / 256, 256>>>();
    k_scan1<<<NB, 1024>>>();
    k_scan2<<<1, 128>>>();
    k_scan3<<<(NN + 255) / 256, 256>>>();
    k_fill<<<(EE + 255) / 256, 256>>>(ei);
    k_gemm1<<<(NN + 63) / 64, 256>>>(x, W1);
    k_gather1<<<(NN * 32 + 255) / 256, 256>>>(b1);
    k_bnstats<<<1024, 128>>>();
    k_bn_final<<<1, 128>>>(gamma, beta);
    k_gemm2<<<(NN + 63) / 64, 256>>>(W2);
    k_gather2<<<(NN * 32 + 255) / 256, 256>>>(b2);
    k_final<<<(NN + 255) / 256, 256>>>(centers, temp, out);
}

// round 5
// speedup vs baseline: 2.1058x; 1.6963x over previous
#include <cuda_runtime.h>

#define NN   100000
#define EE   1600000
#define HID  128
#define EMBD 64
#define KC   100
#define NB   98          // ceil(100000/1024) scan blocks

// ---------------- scratch -----------------------------------------------------
__device__ float g_dis[NN];
__device__ float g_H[NN * HID];
__device__ float g_H1[NN * HID];
__device__ float g_H2[NN * EMBD];
__device__ float g_EMB[NN * EMBD];
__device__ float g_sum[HID];
__device__ float g_sumsq[HID];
__device__ float g_scale[HID];
__device__ float g_shift[HID];
__device__ int   g_cnt[NN];
__device__ int   g_fill[NN];
__device__ int   g_rowstart[NN + 1];
__device__ int   g_blocksum[NB];
__device__ int   g_blockoff[NB];
__device__ int   g_esrc[EE];
__device__ float g_enorm[EE];

// ---------------- init / degree / scan / fill --------------------------------
__global__ void k_init() {
    int i = blockIdx.x * blockDim.x + threadIdx.x;
    if (i < NN)  { g_cnt[i] = 0; g_fill[i] = 0; }
    if (i < HID) { g_sum[i] = 0.f; g_sumsq[i] = 0.f; }
}

__global__ void k_count(const int* __restrict__ ei) {
    int e = blockIdx.x * blockDim.x + threadIdx.x;
    if (e < EE) {
        int dst = ei[EE + e];
        if ((unsigned)dst < NN) atomicAdd(&g_cnt[dst], 1);
    }
}

__global__ void k_dis() {
    int i = blockIdx.x * blockDim.x + threadIdx.x;
    if (i < NN) g_dis[i] = rsqrtf((float)(g_cnt[i] + 1));
}

__global__ void k_scan1() {
    __shared__ int s[1024];
    int t = threadIdx.x;
    int i = blockIdx.x * 1024 + t;
    int v = (i < NN) ? g_cnt[i] : 0;
    s[t] = v;
    __syncthreads();
#pragma unroll
    for (int off = 1; off < 1024; off <<= 1) {
        int add = (t >= off) ? s[t - off] : 0;
        __syncthreads();
        s[t] += add;
        __syncthreads();
    }
    if (i < NN) g_rowstart[i] = s[t] - v;
    if (t == 1023) g_blocksum[blockIdx.x] = s[1023];
}

__global__ void k_scan2() {
    __shared__ int s[128];
    int t = threadIdx.x;
    int v = (t < NB) ? g_blocksum[t] : 0;
    s[t] = v;
    __syncthreads();
#pragma unroll
    for (int off = 1; off < 128; off <<= 1) {
        int add = (t >= off) ? s[t - off] : 0;
        __syncthreads();
        s[t] += add;
        __syncthreads();
    }
    if (t < NB) g_blockoff[t] = s[t] - v;
}

__global__ void k_scan3() {
    int i = blockIdx.x * blockDim.x + threadIdx.x;
    if (i < NN) g_rowstart[i] += g_blockoff[i >> 10];
    if (i == 0) g_rowstart[NN] = EE;
}

__global__ void k_fill(const int* __restrict__ ei) {
    int e = blockIdx.x * blockDim.x + threadIdx.x;
    if (e >= EE) return;
    int src = ei[e];
    int dst = ei[EE + e];
    if ((unsigned)src >= NN || (unsigned)dst >= NN) return;
    int pos = g_rowstart[dst] + atomicAdd(&g_fill[dst], 1);
    g_esrc[pos]  = src;
    g_enorm[pos] = g_dis[src] * g_dis[dst];
}

// ---------------- GEMM1: H = x @ W1  (BM=128, BN=128, BK=16, 8x8/thread) -----
__global__ void __launch_bounds__(256) k_gemm1(const float* __restrict__ x,
                                               const float* __restrict__ W) {
    __shared__ float Xs[16 * 132];   // [k][row], padded
    __shared__ float Ws[16 * 128];   // [k][n]
    int tid  = threadIdx.x;
    int row0 = blockIdx.x * 128;
    int ty = tid >> 4, tx = tid & 15;
    int r0 = ty * 8, c0 = tx * 8;

    int lrow  = tid >> 1;            // 0..127
    int lhalf = (tid & 1) * 8;       // 0 or 8
    int wk = tid >> 4;               // 0..15
    int wn = (tid & 15) * 8;

    float acc[8][8];
#pragma unroll
    for (int i = 0; i < 8; i++)
#pragma unroll
        for (int j = 0; j < 8; j++) acc[i][j] = 0.f;

    for (int kk = 0; kk < 128; kk += 16) {
        int gr = row0 + lrow;
        float4 xa = {0,0,0,0}, xb = {0,0,0,0};
        if (gr < NN) {
            xa = *(const float4*)&x[gr * 128 + kk + lhalf];
            xb = *(const float4*)&x[gr * 128 + kk + lhalf + 4];
        }
        Xs[(lhalf + 0) * 132 + lrow] = xa.x;
        Xs[(lhalf + 1) * 132 + lrow] = xa.y;
        Xs[(lhalf + 2) * 132 + lrow] = xa.z;
        Xs[(lhalf + 3) * 132 + lrow] = xa.w;
        Xs[(lhalf + 4) * 132 + lrow] = xb.x;
        Xs[(lhalf + 5) * 132 + lrow] = xb.y;
        Xs[(lhalf + 6) * 132 + lrow] = xb.z;
        Xs[(lhalf + 7) * 132 + lrow] = xb.w;
        *(float4*)&Ws[wk * 128 + wn]     = *(const float4*)&W[(kk + wk) * 128 + wn];
        *(float4*)&Ws[wk * 128 + wn + 4] = *(const float4*)&W[(kk + wk) * 128 + wn + 4];
        __syncthreads();
#pragma unroll
        for (int k = 0; k < 16; k++) {
            float4 a0 = *(const float4*)&Xs[k * 132 + r0];
            float4 a1 = *(const float4*)&Xs[k * 132 + r0 + 4];
            float4 b0 = *(const float4*)&Ws[k * 128 + c0];
            float4 b1 = *(const float4*)&Ws[k * 128 + c0 + 4];
            float av[8] = {a0.x, a0.y, a0.z, a0.w, a1.x, a1.y, a1.z, a1.w};
            float bv[8] = {b0.x, b0.y, b0.z, b0.w, b1.x, b1.y, b1.z, b1.w};
#pragma unroll
            for (int i = 0; i < 8; i++)
#pragma unroll
                for (int j = 0; j < 8; j++)
                    acc[i][j] = fmaf(av[i], bv[j], acc[i][j]);
        }
        __syncthreads();
    }
#pragma unroll
    for (int i = 0; i < 8; i++) {
        int gr = row0 + r0 + i;
        if (gr < NN) {
            float4 o0 = {acc[i][0], acc[i][1], acc[i][2], acc[i][3]};
            float4 o1 = {acc[i][4], acc[i][5], acc[i][6], acc[i][7]};
            *(float4*)&g_H[gr * 128 + c0]     = o0;
            *(float4*)&g_H[gr * 128 + c0 + 4] = o1;
        }
    }
}

// ---------------- gather 1: warp per node, 128 feats -------------------------
__global__ void k_gather1(const float* __restrict__ b1) {
    int w    = (blockIdx.x * blockDim.x + threadIdx.x) >> 5;
    int lane = threadIdx.x & 31;
    if (w >= NN) return;
    int beg = g_rowstart[w], end = g_rowstart[w + 1];
    float4 acc = {0.f, 0.f, 0.f, 0.f};
    int p = beg;
    for (; p + 4 <= end; p += 4) {
        int   s0 = __ldg(&g_esrc[p]),     s1 = __ldg(&g_esrc[p + 1]);
        int   s2 = __ldg(&g_esrc[p + 2]), s3 = __ldg(&g_esrc[p + 3]);
        float n0 = __ldg(&g_enorm[p]),     n1 = __ldg(&g_enorm[p + 1]);
        float n2 = __ldg(&g_enorm[p + 2]), n3 = __ldg(&g_enorm[p + 3]);
        float4 v0 = *(const float4*)&g_H[s0 * HID + lane * 4];
        float4 v1 = *(const float4*)&g_H[s1 * HID + lane * 4];
        float4 v2 = *(const float4*)&g_H[s2 * HID + lane * 4];
        float4 v3 = *(const float4*)&g_H[s3 * HID + lane * 4];
        acc.x = fmaf(v0.x, n0, acc.x); acc.y = fmaf(v0.y, n0, acc.y);
        acc.z = fmaf(v0.z, n0, acc.z); acc.w = fmaf(v0.w, n0, acc.w);
        acc.x = fmaf(v1.x, n1, acc.x); acc.y = fmaf(v1.y, n1, acc.y);
        acc.z = fmaf(v1.z, n1, acc.z); acc.w = fmaf(v1.w, n1, acc.w);
        acc.x = fmaf(v2.x, n2, acc.x); acc.y = fmaf(v2.y, n2, acc.y);
        acc.z = fmaf(v2.z, n2, acc.z); acc.w = fmaf(v2.w, n2, acc.w);
        acc.x = fmaf(v3.x, n3, acc.x); acc.y = fmaf(v3.y, n3, acc.y);
        acc.z = fmaf(v3.z, n3, acc.z); acc.w = fmaf(v3.w, n3, acc.w);
    }
    for (; p < end; p++) {
        int   s0 = __ldg(&g_esrc[p]);
        float n0 = __ldg(&g_enorm[p]);
        float4 v0 = *(const float4*)&g_H[s0 * HID + lane * 4];
        acc.x = fmaf(v0.x, n0, acc.x); acc.y = fmaf(v0.y, n0, acc.y);
        acc.z = fmaf(v0.z, n0, acc.z); acc.w = fmaf(v0.w, n0, acc.w);
    }
    float dn = g_dis[w];
    float sl = dn * dn;
    float4 h  = *(const float4*)&g_H[w * HID + lane * 4];
    float4 bb = *(const float4*)&b1[lane * 4];
    acc.x += sl * h.x + bb.x;
    acc.y += sl * h.y + bb.y;
    acc.z += sl * h.z + bb.z;
    acc.w += sl * h.w + bb.w;
    *(float4*)&g_H1[w * HID + lane * 4] = acc;
}

// ---------------- BN stats ----------------------------------------------------
__global__ void k_bnstats() {
    int c = threadIdx.x;
    float s = 0.f, s2 = 0.f;
    for (int r = blockIdx.x; r < NN; r += gridDim.x) {
        float v = g_H1[r * HID + c];
        s += v; s2 += v * v;
    }
    atomicAdd(&g_sum[c], s);
    atomicAdd(&g_sumsq[c], s2);
}

__global__ void k_bn_final(const float* __restrict__ gamma, const float* __restrict__ beta) {
    int c = threadIdx.x;
    float mu   = g_sum[c]   * (1.0f / NN);
    float var  = g_sumsq[c] * (1.0f / NN) - mu * mu;
    float istd = rsqrtf(var + 1e-5f);
    float sc   = istd * gamma[c];
    g_scale[c] = sc;
    g_shift[c] = beta[c] - mu * sc;
}

// ---------------- GEMM2 fused BN+ReLU (BM=128, BN=64, BK=16, 4x8/thread) -----
__global__ void __launch_bounds__(256) k_gemm2(const float* __restrict__ W2) {
    __shared__ float Xs[16 * 132];   // [k][row]
    __shared__ float Ws[16 * 64];    // [k][n]
    __shared__ float Ss[128], Hs[128];
    int tid  = threadIdx.x;
    int row0 = blockIdx.x * 128;
    int ty = tid >> 3, tx = tid & 7;     // ty 0..31, tx 0..7
    int r0 = ty * 4, c0 = tx * 8;

    if (tid < 128) { Ss[tid] = g_scale[tid]; Hs[tid] = g_shift[tid]; }

    int lrow  = tid >> 1;
    int lhalf = (tid & 1) * 8;
    int wk = tid >> 4;               // 0..15
    int wn = (tid & 15) * 4;         // 0..60

    float acc[4][8];
#pragma unroll
    for (int i = 0; i < 4; i++)
#pragma unroll
        for (int j = 0; j < 8; j++) acc[i][j] = 0.f;

    __syncthreads();
    for (int kk = 0; kk < 128; kk += 16) {
        int gr = row0 + lrow;
        float v[8] = {0,0,0,0,0,0,0,0};
        if (gr < NN) {
            float4 xa = *(const float4*)&g_H1[gr * 128 + kk + lhalf];
            float4 xb = *(const float4*)&g_H1[gr * 128 + kk + lhalf + 4];
            float xv[8] = {xa.x, xa.y, xa.z, xa.w, xb.x, xb.y, xb.z, xb.w};
#pragma unroll
            for (int j = 0; j < 8; j++) {
                int cc = kk + lhalf + j;
                v[j] = fmaxf(fmaf(xv[j], Ss[cc], Hs[cc]), 0.f);
            }
        }
#pragma unroll
        for (int j = 0; j < 8; j++)
            Xs[(lhalf + j) * 132 + lrow] = v[j];
        *(float4*)&Ws[wk * 64 + wn] = *(const float4*)&W2[(kk + wk) * 64 + wn];
        __syncthreads();
#pragma unroll
        for (int k = 0; k < 16; k++) {
            float4 a0 = *(const float4*)&Xs[k * 132 + r0];
            float4 b0 = *(const float4*)&Ws[k * 64 + c0];
            float4 b1 = *(const float4*)&Ws[k * 64 + c0 + 4];
            float av[4] = {a0.x, a0.y, a0.z, a0.w};
            float bv[8] = {b0.x, b0.y, b0.z, b0.w, b1.x, b1.y, b1.z, b1.w};
#pragma unroll
            for (int i = 0; i < 4; i++)
#pragma unroll
                for (int j = 0; j < 8; j++)
                    acc[i][j] = fmaf(av[i], bv[j], acc[i][j]);
        }
        __syncthreads();
    }
#pragma unroll
    for (int i = 0; i < 4; i++) {
        int gr = row0 + r0 + i;
        if (gr < NN) {
            float4 o0 = {acc[i][0], acc[i][1], acc[i][2], acc[i][3]};
            float4 o1 = {acc[i][4], acc[i][5], acc[i][6], acc[i][7]};
            *(float4*)&g_H2[gr * 64 + c0]     = o0;
            *(float4*)&g_H2[gr * 64 + c0 + 4] = o1;
        }
    }
}

// ---------------- gather 2: warp per node, 64 feats --------------------------
__global__ void k_gather2(const float* __restrict__ b2) {
    int w    = (blockIdx.x * blockDim.x + threadIdx.x) >> 5;
    int lane = threadIdx.x & 31;
    if (w >= NN) return;
    int beg = g_rowstart[w], end = g_rowstart[w + 1];
    float2 acc = {0.f, 0.f};
    int p = beg;
    for (; p + 4 <= end; p += 4) {
        int   s0 = __ldg(&g_esrc[p]),     s1 = __ldg(&g_esrc[p + 1]);
        int   s2 = __ldg(&g_esrc[p + 2]), s3 = __ldg(&g_esrc[p + 3]);
        float n0 = __ldg(&g_enorm[p]),     n1 = __ldg(&g_enorm[p + 1]);
        float n2 = __ldg(&g_enorm[p + 2]), n3 = __ldg(&g_enorm[p + 3]);
        float2 v0 = *(const float2*)&g_H2[s0 * EMBD + lane * 2];
        float2 v1 = *(const float2*)&g_H2[s1 * EMBD + lane * 2];
        float2 v2 = *(const float2*)&g_H2[s2 * EMBD + lane * 2];
        float2 v3 = *(const float2*)&g_H2[s3 * EMBD + lane * 2];
        acc.x = fmaf(v0.x, n0, acc.x); acc.y = fmaf(v0.y, n0, acc.y);
        acc.x = fmaf(v1.x, n1, acc.x); acc.y = fmaf(v1.y, n1, acc.y);
        acc.x = fmaf(v2.x, n2, acc.x); acc.y = fmaf(v2.y, n2, acc.y);
        acc.x = fmaf(v3.x, n3, acc.x); acc.y = fmaf(v3.y, n3, acc.y);
    }
    for (; p < end; p++) {
        int   s0 = __ldg(&g_esrc[p]);
        float n0 = __ldg(&g_enorm[p]);
        float2 v0 = *(const float2*)&g_H2[s0 * EMBD + lane * 2];
        acc.x = fmaf(v0.x, n0, acc.x); acc.y = fmaf(v0.y, n0, acc.y);
    }
    float dn = g_dis[w];
    float sl = dn * dn;
    float2 h  = *(const float2*)&g_H2[w * EMBD + lane * 2];
    float2 bb = *(const float2*)&b2[lane * 2];
    acc.x += sl * h.x + bb.x;
    acc.y += sl * h.y + bb.y;
    *(float2*)&g_EMB[w * EMBD + lane * 2] = acc;
}

// ---------------- final -------------------------------------------------------
__global__ void k_final(const float* __restrict__ centers,
                        const float* __restrict__ temp, float* __restrict__ out) {
    __shared__ float Cs[KC * EMBD];
    int tid = threadIdx.x;
    for (int i = tid; i < KC * EMBD; i += blockDim.x) Cs[i] = centers[i];
    __syncthreads();
    int n = blockIdx.x * blockDim.x + tid;
    if (n >= NN) return;

    float e[EMBD];
    const float4* e4 = (const float4*)&g_EMB[n * EMBD];
    float4* o4 = (float4*)&out[n * EMBD];
#pragma unroll
    for (int i = 0; i < 16; i++) {
        float4 r = e4[i];
        e[4 * i + 0] = r.x; e[4 * i + 1] = r.y; e[4 * i + 2] = r.z; e[4 * i + 3] = r.w;
        o4[i] = r;
    }

    float inv_t = 1.0f / temp[0];
    float mx = -1e30f, s = 0.f;
    for (int k = 0; k < KC; k++) {
        float d0 = 0.f, d1 = 0.f, d2 = 0.f, d3 = 0.f;
#pragma unroll
        for (int j = 0; j < 16; j++) {
            float4 c = *(const float4*)&Cs[k * EMBD + j * 4];
            d0 = fmaf(e[4 * j + 0], c.x, d0);
            d1 = fmaf(e[4 * j + 1], c.y, d1);
            d2 = fmaf(e[4 * j + 2], c.z, d2);
            d3 = fmaf(e[4 * j + 3], c.w, d3);
        }
        float d = ((d0 + d1) + (d2 + d3)) * inv_t;
        if (d > mx) { s = s * __expf(mx - d) + 1.f; mx = d; }
        else        { s += __expf(d - mx); }
    }
    float inv_s = 1.0f / s;
    float* so = out + (size_t)NN * EMBD + (size_t)n * KC;
    for (int k = 0; k < KC; k++) {
        float d0 = 0.f, d1 = 0.f, d2 = 0.f, d3 = 0.f;
#pragma unroll
        for (int j = 0; j < 16; j++) {
            float4 c = *(const float4*)&Cs[k * EMBD + j * 4];
            d0 = fmaf(e[4 * j + 0], c.x, d0);
            d1 = fmaf(e[4 * j + 1], c.y, d1);
            d2 = fmaf(e[4 * j + 2], c.z, d2);
            d3 = fmaf(e[4 * j + 3], c.w, d3);
        }
        float d = ((d0 + d1) + (d2 + d3)) * inv_t;
        so[k] = __expf(d - mx) * inv_s;
    }
}

// -----------------------------------------------------------------------------
extern "C" void kernel_launch(void* const* d_in, const int* in_sizes, int n_in,
                              void* d_out, int out_size) {
    const float* x       = (const float*)d_in[0];
    const int*   ei      = (const int*)d_in[1];
    const float* W1      = (const float*)d_in[2];
    const float* b1      = (const float*)d_in[3];
    const float* gamma   = (const float*)d_in[4];
    const float* beta    = (const float*)d_in[5];
    const float* W2      = (const float*)d_in[6];
    const float* b2      = (const float*)d_in[7];
    const float* centers = (const float*)d_in[8];
    const float* temp    = (const float*)d_in[9];
    float* out = (float*)d_out;

    k_init<<<(NN + 255) / 256, 256>>>();
    k_count<<<(EE + 255) / 256, 256>>>(ei);
    k_dis<<<(NN + 255) / 256, 256>>>();
    k_scan1<<<NB, 1024>>>();
    k_scan2<<<1, 128>>>();
    k_scan3<<<(NN + 255) / 256, 256>>>();
    k_fill<<<(EE + 255) / 256, 256>>>(ei);
    k_gemm1<<<(NN + 127) / 128, 256>>>(x, W1);
    k_gather1<<<(NN * 32 + 255) / 256, 256>>>(b1);
    k_bnstats<<<1024, 128>>>();
    k_bn_final<<<1, 128>>>(gamma, beta);
    k_gemm2<<<(NN + 127) / 128, 256>>>(W2);
    k_gather2<<<(NN * 32 + 255) / 256, 256>>>(b2);
    k_final<<<(NN + 255) / 256, 256>>>(centers, temp, out);
}

// round 9
// speedup vs baseline: 2.1923x; 1.0411x over previous
#include <cuda_runtime.h>
#include <cuda_fp16.h>

#define NN   100000
#define EE   1600000
#define HID  128
#define EMBD 64
#define KC   100
#define NB   98          // ceil(100000/1024) scan blocks

// ---------------- scratch -----------------------------------------------------
__device__ float  g_dis[NN];
__device__ __half g_Hh[NN * HID];      // x @ W1, fp16 storage
__device__ float  g_H1[NN * HID];      // gathered h1 (fp32)
__device__ float  g_H2[NN * EMBD];     // relu(bn(h1)) @ W2 (fp32)
__device__ float  g_sum[HID];
__device__ float  g_sumsq[HID];
__device__ float  g_scale[HID];
__device__ float  g_shift[HID];
__device__ int    g_cnt[NN];
__device__ int    g_fill[NN];
__device__ int    g_rowstart[NN + 1];
__device__ int    g_blocksum[NB];
__device__ int    g_blockoff[NB];
__device__ int    g_esrc[EE];
__device__ float  g_enorm[EE];

struct alignas(16) H8 { __half2 a, b, c, d; };

// ---------------- init / degree / scan / fill --------------------------------
__global__ void k_init() {
    int i = blockIdx.x * blockDim.x + threadIdx.x;
    if (i < NN)  { g_cnt[i] = 0; g_fill[i] = 0; }
    if (i < HID) { g_sum[i] = 0.f; g_sumsq[i] = 0.f; }
}

__global__ void k_count(const int* __restrict__ ei) {
    int e = blockIdx.x * blockDim.x + threadIdx.x;
    if (e < EE) {
        int dst = ei[EE + e];
        if ((unsigned)dst < NN) atomicAdd(&g_cnt[dst], 1);
    }
}

__global__ void k_dis() {
    int i = blockIdx.x * blockDim.x + threadIdx.x;
    if (i < NN) g_dis[i] = rsqrtf((float)(g_cnt[i] + 1));
}

__global__ void k_scan1() {
    __shared__ int s[1024];
    int t = threadIdx.x;
    int i = blockIdx.x * 1024 + t;
    int v = (i < NN) ? g_cnt[i] : 0;
    s[t] = v;
    __syncthreads();
#pragma unroll
    for (int off = 1; off < 1024; off <<= 1) {
        int add = (t >= off) ? s[t - off] : 0;
        __syncthreads();
        s[t] += add;
        __syncthreads();
    }
    if (i < NN) g_rowstart[i] = s[t] - v;
    if (t == 1023) g_blocksum[blockIdx.x] = s[1023];
}

__global__ void k_scan2() {
    __shared__ int s[128];
    int t = threadIdx.x;
    int v = (t < NB) ? g_blocksum[t] : 0;
    s[t] = v;
    __syncthreads();
#pragma unroll
    for (int off = 1; off < 128; off <<= 1) {
        int add = (t >= off) ? s[t - off] : 0;
        __syncthreads();
        s[t] += add;
        __syncthreads();
    }
    if (t < NB) g_blockoff[t] = s[t] - v;
}

__global__ void k_scan3() {
    int i = blockIdx.x * blockDim.x + threadIdx.x;
    if (i < NN) g_rowstart[i] += g_blockoff[i >> 10];
    if (i == 0) g_rowstart[NN] = EE;
}

__global__ void k_fill(const int* __restrict__ ei) {
    int e = blockIdx.x * blockDim.x + threadIdx.x;
    if (e >= EE) return;
    int src = ei[e];
    int dst = ei[EE + e];
    if ((unsigned)src >= NN || (unsigned)dst >= NN) return;
    int pos = g_rowstart[dst] + atomicAdd(&g_fill[dst], 1);
    g_esrc[pos]  = src;
    g_enorm[pos] = g_dis[src] * g_dis[dst];
}

// ---------------- GEMM1: H = x @ W1 -> fp16 (BM=128,BN=128,BK=16,8x8) --------
__global__ void __launch_bounds__(256) k_gemm1(const float* __restrict__ x,
                                               const float* __restrict__ W) {
    __shared__ float Xs[16 * 132];
    __shared__ float Ws[16 * 128];
    int tid  = threadIdx.x;
    int row0 = blockIdx.x * 128;
    int ty = tid >> 4, tx = tid & 15;
    int r0 = ty * 8, c0 = tx * 8;

    int lrow  = tid >> 1;
    int lhalf = (tid & 1) * 8;
    int wk = tid >> 4;
    int wn = (tid & 15) * 8;

    float acc[8][8];
#pragma unroll
    for (int i = 0; i < 8; i++)
#pragma unroll
        for (int j = 0; j < 8; j++) acc[i][j] = 0.f;

    for (int kk = 0; kk < 128; kk += 16) {
        int gr = row0 + lrow;
        float4 xa = {0,0,0,0}, xb = {0,0,0,0};
        if (gr < NN) {
            xa = *(const float4*)&x[gr * 128 + kk + lhalf];
            xb = *(const float4*)&x[gr * 128 + kk + lhalf + 4];
        }
        Xs[(lhalf + 0) * 132 + lrow] = xa.x;
        Xs[(lhalf + 1) * 132 + lrow] = xa.y;
        Xs[(lhalf + 2) * 132 + lrow] = xa.z;
        Xs[(lhalf + 3) * 132 + lrow] = xa.w;
        Xs[(lhalf + 4) * 132 + lrow] = xb.x;
        Xs[(lhalf + 5) * 132 + lrow] = xb.y;
        Xs[(lhalf + 6) * 132 + lrow] = xb.z;
        Xs[(lhalf + 7) * 132 + lrow] = xb.w;
        *(float4*)&Ws[wk * 128 + wn]     = *(const float4*)&W[(kk + wk) * 128 + wn];
        *(float4*)&Ws[wk * 128 + wn + 4] = *(const float4*)&W[(kk + wk) * 128 + wn + 4];
        __syncthreads();
#pragma unroll
        for (int k = 0; k < 16; k++) {
            float4 a0 = *(const float4*)&Xs[k * 132 + r0];
            float4 a1 = *(const float4*)&Xs[k * 132 + r0 + 4];
            float4 b0 = *(const float4*)&Ws[k * 128 + c0];
            float4 b1 = *(const float4*)&Ws[k * 128 + c0 + 4];
            float av[8] = {a0.x, a0.y, a0.z, a0.w, a1.x, a1.y, a1.z, a1.w};
            float bv[8] = {b0.x, b0.y, b0.z, b0.w, b1.x, b1.y, b1.z, b1.w};
#pragma unroll
            for (int i = 0; i < 8; i++)
#pragma unroll
                for (int j = 0; j < 8; j++)
                    acc[i][j] = fmaf(av[i], bv[j], acc[i][j]);
        }
        __syncthreads();
    }
#pragma unroll
    for (int i = 0; i < 8; i++) {
        int gr = row0 + r0 + i;
        if (gr < NN) {
            H8 v;
            v.a = __floats2half2_rn(acc[i][0], acc[i][1]);
            v.b = __floats2half2_rn(acc[i][2], acc[i][3]);
            v.c = __floats2half2_rn(acc[i][4], acc[i][5]);
            v.d = __floats2half2_rn(acc[i][6], acc[i][7]);
            *(H8*)&g_Hh[gr * 128 + c0] = v;
        }
    }
}

// ---------------- gather 1: warp/node, fp16 rows (8B per lane) ---------------
__device__ __forceinline__ void h4_fma(float4& acc, const __half* p, float n) {
    uint2 raw = *(const uint2*)p;
    float2 f0 = __half22float2(*(const __half2*)&raw.x);
    float2 f1 = __half22float2(*(const __half2*)&raw.y);
    acc.x = fmaf(f0.x, n, acc.x); acc.y = fmaf(f0.y, n, acc.y);
    acc.z = fmaf(f1.x, n, acc.z); acc.w = fmaf(f1.y, n, acc.w);
}

__global__ void k_gather1(const float* __restrict__ b1) {
    int w    = (blockIdx.x * blockDim.x + threadIdx.x) >> 5;
    int lane = threadIdx.x & 31;
    if (w >= NN) return;
    int beg = g_rowstart[w], end = g_rowstart[w + 1];
    float4 acc = {0.f, 0.f, 0.f, 0.f};
    int p = beg;
    for (; p + 4 <= end; p += 4) {
        int   s0 = __ldg(&g_esrc[p]),     s1 = __ldg(&g_esrc[p + 1]);
        int   s2 = __ldg(&g_esrc[p + 2]), s3 = __ldg(&g_esrc[p + 3]);
        float n0 = __ldg(&g_enorm[p]),     n1 = __ldg(&g_enorm[p + 1]);
        float n2 = __ldg(&g_enorm[p + 2]), n3 = __ldg(&g_enorm[p + 3]);
        h4_fma(acc, &g_Hh[s0 * HID + lane * 4], n0);
        h4_fma(acc, &g_Hh[s1 * HID + lane * 4], n1);
        h4_fma(acc, &g_Hh[s2 * HID + lane * 4], n2);
        h4_fma(acc, &g_Hh[s3 * HID + lane * 4], n3);
    }
    for (; p < end; p++) {
        int   s0 = __ldg(&g_esrc[p]);
        float n0 = __ldg(&g_enorm[p]);
        h4_fma(acc, &g_Hh[s0 * HID + lane * 4], n0);
    }
    float dn = g_dis[w];
    float sl = dn * dn;
    h4_fma(acc, &g_Hh[w * HID + lane * 4], sl);
    float4 bb = *(const float4*)&b1[lane * 4];
    acc.x += bb.x; acc.y += bb.y; acc.z += bb.z; acc.w += bb.w;
    *(float4*)&g_H1[w * HID + lane * 4] = acc;
}

// ---------------- BN stats ----------------------------------------------------
__global__ void k_bnstats() {
    int c = threadIdx.x;
    float s = 0.f, s2 = 0.f;
    for (int r = blockIdx.x; r < NN; r += gridDim.x) {
        float v = g_H1[r * HID + c];
        s += v; s2 += v * v;
    }
    atomicAdd(&g_sum[c], s);
    atomicAdd(&g_sumsq[c], s2);
}

__global__ void k_bn_final(const float* __restrict__ gamma, const float* __restrict__ beta) {
    int c = threadIdx.x;
    float mu   = g_sum[c]   * (1.0f / NN);
    float var  = g_sumsq[c] * (1.0f / NN) - mu * mu;
    float istd = rsqrtf(var + 1e-5f);
    float sc   = istd * gamma[c];
    g_scale[c] = sc;
    g_shift[c] = beta[c] - mu * sc;
}

// ---------------- GEMM2 fused BN+ReLU (BM=128,BN=64,BK=16,4x8) ---------------
__global__ void __launch_bounds__(256) k_gemm2(const float* __restrict__ W2) {
    __shared__ float Xs[16 * 132];
    __shared__ float Ws[16 * 64];
    __shared__ float Ss[128], Hs[128];
    int tid  = threadIdx.x;
    int row0 = blockIdx.x * 128;
    int ty = tid >> 3, tx = tid & 7;
    int r0 = ty * 4, c0 = tx * 8;

    if (tid < 128) { Ss[tid] = g_scale[tid]; Hs[tid] = g_shift[tid]; }

    int lrow  = tid >> 1;
    int lhalf = (tid & 1) * 8;
    int wk = tid >> 4;
    int wn = (tid & 15) * 4;

    float acc[4][8];
#pragma unroll
    for (int i = 0; i < 4; i++)
#pragma unroll
        for (int j = 0; j < 8; j++) acc[i][j] = 0.f;

    __syncthreads();
    for (int kk = 0; kk < 128; kk += 16) {
        int gr = row0 + lrow;
        float v[8] = {0,0,0,0,0,0,0,0};
        if (gr < NN) {
            float4 xa = *(const float4*)&g_H1[gr * 128 + kk + lhalf];
            float4 xb = *(const float4*)&g_H1[gr * 128 + kk + lhalf + 4];
            float xv[8] = {xa.x, xa.y, xa.z, xa.w, xb.x, xb.y, xb.z, xb.w};
#pragma unroll
            for (int j = 0; j < 8; j++) {
                int cc = kk + lhalf + j;
                v[j] = fmaxf(fmaf(xv[j], Ss[cc], Hs[cc]), 0.f);
            }
        }
#pragma unroll
        for (int j = 0; j < 8; j++)
            Xs[(lhalf + j) * 132 + lrow] = v[j];
        *(float4*)&Ws[wk * 64 + wn] = *(const float4*)&W2[(kk + wk) * 64 + wn];
        __syncthreads();
#pragma unroll
        for (int k = 0; k < 16; k++) {
            float4 a0 = *(const float4*)&Xs[k * 132 + r0];
            float4 b0 = *(const float4*)&Ws[k * 64 + c0];
            float4 b1 = *(const float4*)&Ws[k * 64 + c0 + 4];
            float av[4] = {a0.x, a0.y, a0.z, a0.w};
            float bv[8] = {b0.x, b0.y, b0.z, b0.w, b1.x, b1.y, b1.z, b1.w};
#pragma unroll
            for (int i = 0; i < 4; i++)
#pragma unroll
                for (int j = 0; j < 8; j++)
                    acc[i][j] = fmaf(av[i], bv[j], acc[i][j]);
        }
        __syncthreads();
    }
#pragma unroll
    for (int i = 0; i < 4; i++) {
        int gr = row0 + r0 + i;
        if (gr < NN) {
            float4 o0 = {acc[i][0], acc[i][1], acc[i][2], acc[i][3]};
            float4 o1 = {acc[i][4], acc[i][5], acc[i][6], acc[i][7]};
            *(float4*)&g_H2[gr * 64 + c0]     = o0;
            *(float4*)&g_H2[gr * 64 + c0 + 4] = o1;
        }
    }
}

// ---------------- gather 2: warp/node, 64 feats, writes emb to out -----------
__global__ void k_gather2(const float* __restrict__ b2, float* __restrict__ out) {
    int w    = (blockIdx.x * blockDim.x + threadIdx.x) >> 5;
    int lane = threadIdx.x & 31;
    if (w >= NN) return;
    int beg = g_rowstart[w], end = g_rowstart[w + 1];
    float2 acc = {0.f, 0.f};
    int p = beg;
    for (; p + 4 <= end; p += 4) {
        int   s0 = __ldg(&g_esrc[p]),     s1 = __ldg(&g_esrc[p + 1]);
        int   s2 = __ldg(&g_esrc[p + 2]), s3 = __ldg(&g_esrc[p + 3]);
        float n0 = __ldg(&g_enorm[p]),     n1 = __ldg(&g_enorm[p + 1]);
        float n2 = __ldg(&g_enorm[p + 2]), n3 = __ldg(&g_enorm[p + 3]);
        float2 v0 = *(const float2*)&g_H2[s0 * EMBD + lane * 2];
        float2 v1 = *(const float2*)&g_H2[s1 * EMBD + lane * 2];
        float2 v2 = *(const float2*)&g_H2[s2 * EMBD + lane * 2];
        float2 v3 = *(const float2*)&g_H2[s3 * EMBD + lane * 2];
        acc.x = fmaf(v0.x, n0, acc.x); acc.y = fmaf(v0.y, n0, acc.y);
        acc.x = fmaf(v1.x, n1, acc.x); acc.y = fmaf(v1.y, n1, acc.y);
        acc.x = fmaf(v2.x, n2, acc.x); acc.y = fmaf(v2.y, n2, acc.y);
        acc.x = fmaf(v3.x, n3, acc.x); acc.y = fmaf(v3.y, n3, acc.y);
    }
    for (; p < end; p++) {
        int   s0 = __ldg(&g_esrc[p]);
        float n0 = __ldg(&g_enorm[p]);
        float2 v0 = *(const float2*)&g_H2[s0 * EMBD + lane * 2];
        acc.x = fmaf(v0.x, n0, acc.x); acc.y = fmaf(v0.y, n0, acc.y);
    }
    float dn = g_dis[w];
    float sl = dn * dn;
    float2 h  = *(const float2*)&g_H2[w * EMBD + lane * 2];
    float2 bb = *(const float2*)&b2[lane * 2];
    acc.x += sl * h.x + bb.x;
    acc.y += sl * h.y + bb.y;
    *(float2*)&out[w * EMBD + lane * 2] = acc;
}

// ---------------- final: softmax(emb @ centers^T / T), single dot pass -------
__global__ void k_final(const float* __restrict__ centers,
                        const float* __restrict__ temp, float* __restrict__ out) {
    __shared__ float Cs[KC * EMBD];
    int tid = threadIdx.x;
    for (int i = tid; i < KC * EMBD; i += blockDim.x) Cs[i] = centers[i];
    __syncthreads();
    int n = blockIdx.x * blockDim.x + tid;
    if (n >= NN) return;

    float e[EMBD];
    const float4* e4 = (const float4*)&out[n * EMBD];   // emb written by gather2
#pragma unroll
    for (int i = 0; i < 16; i++) {
        float4 r = e4[i];
        e[4 * i + 0] = r.x; e[4 * i + 1] = r.y; e[4 * i + 2] = r.z; e[4 * i + 3] = r.w;
    }

    float inv_t = 1.0f / temp[0];
    float lg[KC];                 // local memory: logits buffer
    float mx = -1e30f;
#pragma unroll 1
    for (int k = 0; k < KC; k++) {
        float d0 = 0.f, d1 = 0.f, d2 = 0.f, d3 = 0.f;
#pragma unroll
        for (int j = 0; j < 16; j++) {
            float4 c = *(const float4*)&Cs[k * EMBD + j * 4];
            d0 = fmaf(e[4 * j + 0], c.x, d0);
            d1 = fmaf(e[4 * j + 1], c.y, d1);
            d2 = fmaf(e[4 * j + 2], c.z, d2);
            d3 = fmaf(e[4 * j + 3], c.w, d3);
        }
        float d = ((d0 + d1) + (d2 + d3)) * inv_t;
        lg[k] = d;
        mx = fmaxf(mx, d);
    }
    float s = 0.f;
#pragma unroll 1
    for (int k = 0; k < KC; k++) {
        float ex = __expf(lg[k] - mx);
        lg[k] = ex;
        s += ex;
    }
    float inv_s = 1.0f / s;
    float* so = out + (size_t)NN * EMBD + (size_t)n * KC;
#pragma unroll 1
    for (int k = 0; k < KC; k++) so[k] = lg[k] * inv_s;
}

// -----------------------------------------------------------------------------
extern "C" void kernel_launch(void* const* d_in, const int* in_sizes, int n_in,
                              void* d_out, int out_size) {
    const float* x       = (const float*)d_in[0];
    const int*   ei      = (const int*)d_in[1];
    const float* W1      = (const float*)d_in[2];
    const float* b1      = (const float*)d_in[3];
    const float* gamma   = (const float*)d_in[4];
    const float* beta    = (const float*)d_in[5];
    const float* W2      = (const float*)d_in[6];
    const float* b2      = (const float*)d_in[7];
    const float* centers = (const float*)d_in[8];
    const float* temp    = (const float*)d_in[9];
    float* out = (float*)d_out;

    k_init<<<(NN + 255) / 256, 256>>>();
    k_count<<<(EE + 255) / 256, 256>>>(ei);
    k_dis<<<(NN + 255) / 256, 256>>>();
    k_scan1<<<NB, 1024>>>();
    k_scan2<<<1, 128>>>();
    k_scan3<<<(NN + 255) / 256, 256>>>();
    k_fill<<<(EE + 255) / 256, 256>>>(ei);
    k_gemm1<<<(NN + 127) / 128, 256>>>(x, W1);
    k_gather1<<<(NN * 32 + 255) / 256, 256>>>(b1);
    k_bnstats<<<1024, 128>>>();
    k_bn_final<<<1, 128>>>(gamma, beta);
    k_gemm2<<<(NN + 127) / 128, 256>>>(W2);
    k_gather2<<<(NN * 32 + 255) / 256, 256>>>(b2, out);
    k_final<<<(NN + 255) / 256, 256>>>(centers, temp, out);
}

// round 10
// speedup vs baseline: 2.4963x; 1.1387x over previous
#include <cuda_runtime.h>
#include <cuda_fp16.h>

#define NN   100000
#define EE   1600000
#define HID  128
#define EMBD 64
#define KC   100
#define NB   98          // ceil(100000/1024) scan blocks

// ---------------- scratch -----------------------------------------------------
__device__ float  g_dis[NN];
__device__ __half g_Hh[NN * HID];      // x @ W1, fp16 storage
__device__ float  g_H1[NN * HID];      // gathered h1 (fp32)
__device__ __half g_H2h[NN * EMBD];    // relu(bn(h1)) @ W2, fp16 storage
__device__ float  g_mx[NN];            // softmax row max
__device__ float  g_is[NN];            // softmax 1/sum
__device__ float  g_sum[HID];
__device__ float  g_sumsq[HID];
__device__ float  g_scale[HID];
__device__ float  g_shift[HID];
__device__ int    g_cnt[NN];
__device__ int    g_fill[NN];
__device__ int    g_rowstart[NN + 1];
__device__ int    g_blocksum[NB];
__device__ int    g_blockoff[NB];
__device__ int    g_esrc[EE];
__device__ float  g_enorm[EE];

struct alignas(16) H8 { __half2 a, b, c, d; };

// ---------------- init / degree / scan / fill --------------------------------
__global__ void k_init() {
    int i = blockIdx.x * blockDim.x + threadIdx.x;
    if (i < NN)  { g_cnt[i] = 0; g_fill[i] = 0; }
    if (i < HID) { g_sum[i] = 0.f; g_sumsq[i] = 0.f; }
}

__global__ void k_count(const int* __restrict__ ei) {
    int e = blockIdx.x * blockDim.x + threadIdx.x;
    if (e < EE) {
        int dst = ei[EE + e];
        if ((unsigned)dst < NN) atomicAdd(&g_cnt[dst], 1);
    }
}

__global__ void k_dis() {
    int i = blockIdx.x * blockDim.x + threadIdx.x;
    if (i < NN) g_dis[i] = rsqrtf((float)(g_cnt[i] + 1));
}

__global__ void k_scan1() {
    __shared__ int s[1024];
    int t = threadIdx.x;
    int i = blockIdx.x * 1024 + t;
    int v = (i < NN) ? g_cnt[i] : 0;
    s[t] = v;
    __syncthreads();
#pragma unroll
    for (int off = 1; off < 1024; off <<= 1) {
        int add = (t >= off) ? s[t - off] : 0;
        __syncthreads();
        s[t] += add;
        __syncthreads();
    }
    if (i < NN) g_rowstart[i] = s[t] - v;
    if (t == 1023) g_blocksum[blockIdx.x] = s[1023];
}

__global__ void k_scan2() {
    __shared__ int s[128];
    int t = threadIdx.x;
    int v = (t < NB) ? g_blocksum[t] : 0;
    s[t] = v;
    __syncthreads();
#pragma unroll
    for (int off = 1; off < 128; off <<= 1) {
        int add = (t >= off) ? s[t - off] : 0;
        __syncthreads();
        s[t] += add;
        __syncthreads();
    }
    if (t < NB) g_blockoff[t] = s[t] - v;
}

__global__ void k_scan3() {
    int i = blockIdx.x * blockDim.x + threadIdx.x;
    if (i < NN) g_rowstart[i] += g_blockoff[i >> 10];
    if (i == 0) g_rowstart[NN] = EE;
}

__global__ void k_fill(const int* __restrict__ ei) {
    int e = blockIdx.x * blockDim.x + threadIdx.x;
    if (e >= EE) return;
    int src = ei[e];
    int dst = ei[EE + e];
    if ((unsigned)src >= NN || (unsigned)dst >= NN) return;
    int pos = g_rowstart[dst] + atomicAdd(&g_fill[dst], 1);
    g_esrc[pos]  = src;
    g_enorm[pos] = g_dis[src] * g_dis[dst];
}

// ---------------- GEMM1: H = x @ W1 -> fp16 (BM=128,BN=128,BK=16,8x8) --------
__global__ void __launch_bounds__(256) k_gemm1(const float* __restrict__ x,
                                               const float* __restrict__ W) {
    __shared__ float Xs[16 * 132];
    __shared__ float Ws[16 * 128];
    int tid  = threadIdx.x;
    int row0 = blockIdx.x * 128;
    int ty = tid >> 4, tx = tid & 15;
    int r0 = ty * 8, c0 = tx * 8;

    int lrow  = tid >> 1;
    int lhalf = (tid & 1) * 8;
    int wk = tid >> 4;
    int wn = (tid & 15) * 8;

    float acc[8][8];
#pragma unroll
    for (int i = 0; i < 8; i++)
#pragma unroll
        for (int j = 0; j < 8; j++) acc[i][j] = 0.f;

    for (int kk = 0; kk < 128; kk += 16) {
        int gr = row0 + lrow;
        float4 xa = {0,0,0,0}, xb = {0,0,0,0};
        if (gr < NN) {
            xa = *(const float4*)&x[gr * 128 + kk + lhalf];
            xb = *(const float4*)&x[gr * 128 + kk + lhalf + 4];
        }
        Xs[(lhalf + 0) * 132 + lrow] = xa.x;
        Xs[(lhalf + 1) * 132 + lrow] = xa.y;
        Xs[(lhalf + 2) * 132 + lrow] = xa.z;
        Xs[(lhalf + 3) * 132 + lrow] = xa.w;
        Xs[(lhalf + 4) * 132 + lrow] = xb.x;
        Xs[(lhalf + 5) * 132 + lrow] = xb.y;
        Xs[(lhalf + 6) * 132 + lrow] = xb.z;
        Xs[(lhalf + 7) * 132 + lrow] = xb.w;
        *(float4*)&Ws[wk * 128 + wn]     = *(const float4*)&W[(kk + wk) * 128 + wn];
        *(float4*)&Ws[wk * 128 + wn + 4] = *(const float4*)&W[(kk + wk) * 128 + wn + 4];
        __syncthreads();
#pragma unroll
        for (int k = 0; k < 16; k++) {
            float4 a0 = *(const float4*)&Xs[k * 132 + r0];
            float4 a1 = *(const float4*)&Xs[k * 132 + r0 + 4];
            float4 b0 = *(const float4*)&Ws[k * 128 + c0];
            float4 b1 = *(const float4*)&Ws[k * 128 + c0 + 4];
            float av[8] = {a0.x, a0.y, a0.z, a0.w, a1.x, a1.y, a1.z, a1.w};
            float bv[8] = {b0.x, b0.y, b0.z, b0.w, b1.x, b1.y, b1.z, b1.w};
#pragma unroll
            for (int i = 0; i < 8; i++)
#pragma unroll
                for (int j = 0; j < 8; j++)
                    acc[i][j] = fmaf(av[i], bv[j], acc[i][j]);
        }
        __syncthreads();
    }
#pragma unroll
    for (int i = 0; i < 8; i++) {
        int gr = row0 + r0 + i;
        if (gr < NN) {
            H8 v;
            v.a = __floats2half2_rn(acc[i][0], acc[i][1]);
            v.b = __floats2half2_rn(acc[i][2], acc[i][3]);
            v.c = __floats2half2_rn(acc[i][4], acc[i][5]);
            v.d = __floats2half2_rn(acc[i][6], acc[i][7]);
            *(H8*)&g_Hh[gr * 128 + c0] = v;
        }
    }
}

// ---------------- gather 1: warp/node, fp16 rows (8B per lane) ---------------
__device__ __forceinline__ void h4_fma(float4& acc, const __half* p, float n) {
    uint2 raw = *(const uint2*)p;
    float2 f0 = __half22float2(*(const __half2*)&raw.x);
    float2 f1 = __half22float2(*(const __half2*)&raw.y);
    acc.x = fmaf(f0.x, n, acc.x); acc.y = fmaf(f0.y, n, acc.y);
    acc.z = fmaf(f1.x, n, acc.z); acc.w = fmaf(f1.y, n, acc.w);
}

__global__ void k_gather1(const float* __restrict__ b1) {
    int w    = (blockIdx.x * blockDim.x + threadIdx.x) >> 5;
    int lane = threadIdx.x & 31;
    if (w >= NN) return;
    int beg = g_rowstart[w], end = g_rowstart[w + 1];
    float4 acc = {0.f, 0.f, 0.f, 0.f};
    int p = beg;
    for (; p + 4 <= end; p += 4) {
        int   s0 = __ldg(&g_esrc[p]),     s1 = __ldg(&g_esrc[p + 1]);
        int   s2 = __ldg(&g_esrc[p + 2]), s3 = __ldg(&g_esrc[p + 3]);
        float n0 = __ldg(&g_enorm[p]),     n1 = __ldg(&g_enorm[p + 1]);
        float n2 = __ldg(&g_enorm[p + 2]), n3 = __ldg(&g_enorm[p + 3]);
        h4_fma(acc, &g_Hh[s0 * HID + lane * 4], n0);
        h4_fma(acc, &g_Hh[s1 * HID + lane * 4], n1);
        h4_fma(acc, &g_Hh[s2 * HID + lane * 4], n2);
        h4_fma(acc, &g_Hh[s3 * HID + lane * 4], n3);
    }
    for (; p < end; p++) {
        int   s0 = __ldg(&g_esrc[p]);
        float n0 = __ldg(&g_enorm[p]);
        h4_fma(acc, &g_Hh[s0 * HID + lane * 4], n0);
    }
    float dn = g_dis[w];
    float sl = dn * dn;
    h4_fma(acc, &g_Hh[w * HID + lane * 4], sl);
    float4 bb = *(const float4*)&b1[lane * 4];
    acc.x += bb.x; acc.y += bb.y; acc.z += bb.z; acc.w += bb.w;
    *(float4*)&g_H1[w * HID + lane * 4] = acc;
}

// ---------------- BN stats ----------------------------------------------------
__global__ void k_bnstats() {
    int c = threadIdx.x;
    float s = 0.f, s2 = 0.f;
    for (int r = blockIdx.x; r < NN; r += gridDim.x) {
        float v = g_H1[r * HID + c];
        s += v; s2 += v * v;
    }
    atomicAdd(&g_sum[c], s);
    atomicAdd(&g_sumsq[c], s2);
}

__global__ void k_bn_final(const float* __restrict__ gamma, const float* __restrict__ beta) {
    int c = threadIdx.x;
    float mu   = g_sum[c]   * (1.0f / NN);
    float var  = g_sumsq[c] * (1.0f / NN) - mu * mu;
    float istd = rsqrtf(var + 1e-5f);
    float sc   = istd * gamma[c];
    g_scale[c] = sc;
    g_shift[c] = beta[c] - mu * sc;
}

// ---------------- GEMM2 fused BN+ReLU -> fp16 (BM=128,BN=64,BK=16,4x8) -------
__global__ void __launch_bounds__(256) k_gemm2(const float* __restrict__ W2) {
    __shared__ float Xs[16 * 132];
    __shared__ float Ws[16 * 64];
    __shared__ float Ss[128], Hs[128];
    int tid  = threadIdx.x;
    int row0 = blockIdx.x * 128;
    int ty = tid >> 3, tx = tid & 7;
    int r0 = ty * 4, c0 = tx * 8;

    if (tid < 128) { Ss[tid] = g_scale[tid]; Hs[tid] = g_shift[tid]; }

    int lrow  = tid >> 1;
    int lhalf = (tid & 1) * 8;
    int wk = tid >> 4;
    int wn = (tid & 15) * 4;

    float acc[4][8];
#pragma unroll
    for (int i = 0; i < 4; i++)
#pragma unroll
        for (int j = 0; j < 8; j++) acc[i][j] = 0.f;

    __syncthreads();
    for (int kk = 0; kk < 128; kk += 16) {
        int gr = row0 + lrow;
        float v[8] = {0,0,0,0,0,0,0,0};
        if (gr < NN) {
            float4 xa = *(const float4*)&g_H1[gr * 128 + kk + lhalf];
            float4 xb = *(const float4*)&g_H1[gr * 128 + kk + lhalf + 4];
            float xv[8] = {xa.x, xa.y, xa.z, xa.w, xb.x, xb.y, xb.z, xb.w};
#pragma unroll
            for (int j = 0; j < 8; j++) {
                int cc = kk + lhalf + j;
                v[j] = fmaxf(fmaf(xv[j], Ss[cc], Hs[cc]), 0.f);
            }
        }
#pragma unroll
        for (int j = 0; j < 8; j++)
            Xs[(lhalf + j) * 132 + lrow] = v[j];
        *(float4*)&Ws[wk * 64 + wn] = *(const float4*)&W2[(kk + wk) * 64 + wn];
        __syncthreads();
#pragma unroll
        for (int k = 0; k < 16; k++) {
            float4 a0 = *(const float4*)&Xs[k * 132 + r0];
            float4 b0 = *(const float4*)&Ws[k * 64 + c0];
            float4 b1 = *(const float4*)&Ws[k * 64 + c0 + 4];
            float av[4] = {a0.x, a0.y, a0.z, a0.w};
            float bv[8] = {b0.x, b0.y, b0.z, b0.w, b1.x, b1.y, b1.z, b1.w};
#pragma unroll
            for (int i = 0; i < 4; i++)
#pragma unroll
                for (int j = 0; j < 8; j++)
                    acc[i][j] = fmaf(av[i], bv[j], acc[i][j]);
        }
        __syncthreads();
    }
#pragma unroll
    for (int i = 0; i < 4; i++) {
        int gr = row0 + r0 + i;
        if (gr < NN) {
            H8 v;
            v.a = __floats2half2_rn(acc[i][0], acc[i][1]);
            v.b = __floats2half2_rn(acc[i][2], acc[i][3]);
            v.c = __floats2half2_rn(acc[i][4], acc[i][5]);
            v.d = __floats2half2_rn(acc[i][6], acc[i][7]);
            *(H8*)&g_H2h[gr * 64 + c0] = v;
        }
    }
}

// ---------------- gather 2: warp/node, fp16 rows (4B per lane) ---------------
__global__ void k_gather2(const float* __restrict__ b2, float* __restrict__ out) {
    int w    = (blockIdx.x * blockDim.x + threadIdx.x) >> 5;
    int lane = threadIdx.x & 31;
    if (w >= NN) return;
    int beg = g_rowstart[w], end = g_rowstart[w + 1];
    float2 acc = {0.f, 0.f};
    int p = beg;
    for (; p + 4 <= end; p += 4) {
        int   s0 = __ldg(&g_esrc[p]),     s1 = __ldg(&g_esrc[p + 1]);
        int   s2 = __ldg(&g_esrc[p + 2]), s3 = __ldg(&g_esrc[p + 3]);
        float n0 = __ldg(&g_enorm[p]),     n1 = __ldg(&g_enorm[p + 1]);
        float n2 = __ldg(&g_enorm[p + 2]), n3 = __ldg(&g_enorm[p + 3]);
        float2 v0 = __half22float2(*(const __half2*)&g_H2h[s0 * EMBD + lane * 2]);
        float2 v1 = __half22float2(*(const __half2*)&g_H2h[s1 * EMBD + lane * 2]);
        float2 v2 = __half22float2(*(const __half2*)&g_H2h[s2 * EMBD + lane * 2]);
        float2 v3 = __half22float2(*(const __half2*)&g_H2h[s3 * EMBD + lane * 2]);
        acc.x = fmaf(v0.x, n0, acc.x); acc.y = fmaf(v0.y, n0, acc.y);
        acc.x = fmaf(v1.x, n1, acc.x); acc.y = fmaf(v1.y, n1, acc.y);
        acc.x = fmaf(v2.x, n2, acc.x); acc.y = fmaf(v2.y, n2, acc.y);
        acc.x = fmaf(v3.x, n3, acc.x); acc.y = fmaf(v3.y, n3, acc.y);
    }
    for (; p < end; p++) {
        int   s0 = __ldg(&g_esrc[p]);
        float n0 = __ldg(&g_enorm[p]);
        float2 v0 = __half22float2(*(const __half2*)&g_H2h[s0 * EMBD + lane * 2]);
        acc.x = fmaf(v0.x, n0, acc.x); acc.y = fmaf(v0.y, n0, acc.y);
    }
    float dn = g_dis[w];
    float sl = dn * dn;
    float2 h  = __half22float2(*(const __half2*)&g_H2h[w * EMBD + lane * 2]);
    float2 bb = *(const float2*)&b2[lane * 2];
    acc.x += sl * h.x + bb.x;
    acc.y += sl * h.y + bb.y;
    *(float2*)&out[w * EMBD + lane * 2] = acc;
}

// ---------------- logits + online softmax stats (no spills) ------------------
__global__ void __launch_bounds__(256) k_logits(const float* __restrict__ centers,
                                                const float* __restrict__ temp,
                                                float* __restrict__ out) {
    __shared__ float Cs[KC * EMBD];
    int tid = threadIdx.x;
    for (int i = tid; i < KC * EMBD; i += blockDim.x) Cs[i] = centers[i];
    __syncthreads();
    int n = blockIdx.x * blockDim.x + tid;
    if (n >= NN) return;

    float e[EMBD];
    const float4* e4 = (const float4*)&out[n * EMBD];   // emb written by gather2
#pragma unroll
    for (int i = 0; i < 16; i++) {
        float4 r = e4[i];
        e[4 * i + 0] = r.x; e[4 * i + 1] = r.y; e[4 * i + 2] = r.z; e[4 * i + 3] = r.w;
    }

    float inv_t = 1.0f / temp[0];
    float* so = out + (size_t)NN * EMBD + (size_t)n * KC;
    float mx = -1e30f, s = 0.f;
#pragma unroll 1
    for (int k = 0; k < KC; k++) {
        float d0 = 0.f, d1 = 0.f, d2 = 0.f, d3 = 0.f;
#pragma unroll
        for (int j = 0; j < 16; j++) {
            float4 c = *(const float4*)&Cs[k * EMBD + j * 4];
            d0 = fmaf(e[4 * j + 0], c.x, d0);
            d1 = fmaf(e[4 * j + 1], c.y, d1);
            d2 = fmaf(e[4 * j + 2], c.z, d2);
            d3 = fmaf(e[4 * j + 3], c.w, d3);
        }
        float d = ((d0 + d1) + (d2 + d3)) * inv_t;
        so[k] = d;                               // raw logit to global
        if (d > mx) { s = s * __expf(mx - d) + 1.f; mx = d; }
        else        { s += __expf(d - mx); }
    }
    g_mx[n] = mx;
    g_is[n] = 1.0f / s;
}

// ---------------- softmax normalize pass -------------------------------------
__global__ void k_soft(float* __restrict__ out) {
    long long i = (long long)blockIdx.x * blockDim.x + threadIdx.x;
    if (i >= (long long)NN * KC) return;
    int n = (int)(i / KC);
    float* so = out + (size_t)NN * EMBD;
    float d = so[i];
    so[i] = __expf(d - g_mx[n]) * g_is[n];
}

// -----------------------------------------------------------------------------
extern "C" void kernel_launch(void* const* d_in, const int* in_sizes, int n_in,
                              void* d_out, int out_size) {
    const float* x       = (const float*)d_in[0];
    const int*   ei      = (const int*)d_in[1];
    const float* W1      = (const float*)d_in[2];
    const float* b1      = (const float*)d_in[3];
    const float* gamma   = (const float*)d_in[4];
    const float* beta    = (const float*)d_in[5];
    const float* W2      = (const float*)d_in[6];
    const float* b2      = (const float*)d_in[7];
    const float* centers = (const float*)d_in[8];
    const float* temp    = (const float*)d_in[9];
    float* out = (float*)d_out;

    k_init<<<(NN + 255) / 256, 256>>>();
    k_count<<<(EE + 255) / 256, 256>>>(ei);
    k_dis<<<(NN + 255) / 256, 256>>>();
    k_scan1<<<NB, 1024>>>();
    k_scan2<<<1, 128>>>();
    k_scan3<<<(NN + 255) / 256, 256>>>();
    k_fill<<<(EE + 255) / 256, 256>>>(ei);
    k_gemm1<<<(NN + 127) / 128, 256>>>(x, W1);
    k_gather1<<<(NN * 32 + 255) / 256, 256>>>(b1);
    k_bnstats<<<1024, 128>>>();
    k_bn_final<<<1, 128>>>(gamma, beta);
    k_gemm2<<<(NN + 127) / 128, 256>>>(W2);
    k_gather2<<<(NN * 32 + 255) / 256, 256>>>(b2, out);
    k_logits<<<(NN + 255) / 256, 256>>>(centers, temp, out);
    k_soft<<<(NN * KC + 255) / 256, 256>>>(out);
}